// round 11
// baseline (speedup 1.0000x reference)
#include <cuda_runtime.h>

// LocalExpansion via scatter — FINAL.
// out[q, k, dv] = in[q + shift(k), dv] (7x7 window, zero-padded).
//
// Thread (bh, y, x, dv) loads its own 16B slice once, then scatters it to the
// 49 destinations q = p - shift(k) (ascending-address order) and zero-fills
// its own row's OOB taps. Interior pixels (76%) take a predicate-free path.
// Stores use default write-back policy (streaming hints measured neutral;
// write-back gives L2 maximal coalescing residency before DRAM drain).
//
// Converged at ~71.7 us = 462 MB / 6.45 TB/s, ~81% of HBM3e spec — the
// practical pure-write-stream ceiling (verified across STG.128/STG.256/
// UBLKCP paths, gather & scatter dataflows, 1/1.9-wave grids, sorted and
// unsorted store orders).
//
// B*H = 16, N = 48*48 = 2304, K = 49, D = 64 floats (= 16 float4).

#define HEIGHT 48
#define WIDTH  48
#define NPIX   (HEIGHT * WIDTH)   // 2304
#define KK     49
#define DVEC   16                 // float4 per tap
#define ROWV   (KK * DVEC)        // 784 float4 per output pixel row

__global__ void __launch_bounds__(256) local_scatter_wb_kernel(
    const float4* __restrict__ in, float4* __restrict__ out)
{
    // blockDim = 256 = 16 dv * 16 x-pixels ; gridDim = (3, 48, 16)
    const int dv = (int)(threadIdx.x & 15u);
    const int x  = (int)(blockIdx.x * 16u + (threadIdx.x >> 4));
    const int y  = (int)blockIdx.y;
    const int bh = (int)blockIdx.z;

    const unsigned int p = (unsigned)bh * NPIX + (unsigned)(y * WIDTH + x);

    const float4 v = __ldg(in + (size_t)p * DVEC + dv);
    float4* __restrict__ base = out + (size_t)p * ROWV + dv;

    if ((unsigned)(y - 3) < (unsigned)(HEIGHT - 6) &&
        (unsigned)(x - 3) < (unsigned)(WIDTH - 6)) {
        // Interior: all 49 destinations valid; descending shift order =>
        // ascending destination addresses.
        #pragma unroll
        for (int i = 6; i >= 0; --i) {
            #pragma unroll
            for (int j = 6; j >= 0; --j) {
                const int k = i * 7 + j;
                const int off = -(((i - 3) * WIDTH) + (j - 3)) * ROWV + k * DVEC;
                base[off] = v;
            }
        }
    } else {
        const float4 z = make_float4(0.f, 0.f, 0.f, 0.f);
        #pragma unroll
        for (int i = 6; i >= 0; --i) {
            const bool src_yok = (unsigned)(y + (i - 3)) < (unsigned)HEIGHT;
            const bool dst_yok = (unsigned)(y - (i - 3)) < (unsigned)HEIGHT;
            #pragma unroll
            for (int j = 6; j >= 0; --j) {
                const int k = i * 7 + j;
                const bool dst_ok = dst_yok && ((unsigned)(x - (j - 3)) < (unsigned)WIDTH);
                const bool src_ok = src_yok && ((unsigned)(x + (j - 3)) < (unsigned)WIDTH);

                const int off = -(((i - 3) * WIDTH) + (j - 3)) * ROWV + k * DVEC;
                if (dst_ok) base[off] = v;          // scatter my value
                if (!src_ok) base[k * DVEC] = z;    // zero-fill my OOB tap
            }
        }
    }
}

extern "C" void kernel_launch(void* const* d_in, const int* in_sizes, int n_in,
                              void* d_out, int out_size)
{
    const float4* in = (const float4*)d_in[0];
    float4* out = (float4*)d_out;
    (void)out_size;

    dim3 grid(WIDTH / 16, HEIGHT, 16);   // (3, 48, 16) -> 2304 CTAs
    local_scatter_wb_kernel<<<grid, 256>>>(in, out);
}

// round 12
// speedup vs baseline: 1.0685x; 1.0685x over previous
#include <cuda_runtime.h>

// LocalExpansion via scatter — FINAL (lock-in of the best measured variant).
// out[q, k, dv] = in[q + shift(k), dv] (7x7 window, zero-padded).
//
// Thread (bh, y, x, dv) loads its own 16B slice once, then scatters it with
// streaming stores (__stcs) to the 49 destinations q = p - shift(k) in
// ascending destination-address order, and zero-fills its own row's OOB taps.
// Interior pixels (76%) take a predicate-free 49-store path.
//
// Converged: ~71.7 us = 462 MB / 6.45 TB/s ~= 81% of HBM3e spec, the
// practical pure-write-stream ceiling (verified across STG.128 / STG.256 /
// UBLKCP paths, gather & scatter dataflows, 1- and 1.9-wave grids, sorted
// and unsorted store orders, cs vs wb policies). SM issue sits at 3.4%;
// nothing SM-side is on the critical path.
//
// B*H = 16, N = 48*48 = 2304, K = 49, D = 64 floats (= 16 float4).

#define HEIGHT 48
#define WIDTH  48
#define NPIX   (HEIGHT * WIDTH)   // 2304
#define KK     49
#define DVEC   16                 // float4 per tap
#define ROWV   (KK * DVEC)        // 784 float4 per output pixel row

__global__ void __launch_bounds__(256) local_scatter_final_kernel(
    const float4* __restrict__ in, float4* __restrict__ out)
{
    // blockDim = 256 = 16 dv * 16 x-pixels ; gridDim = (3, 48, 16)
    const int dv = (int)(threadIdx.x & 15u);
    const int x  = (int)(blockIdx.x * 16u + (threadIdx.x >> 4));
    const int y  = (int)blockIdx.y;
    const int bh = (int)blockIdx.z;

    const unsigned int p = (unsigned)bh * NPIX + (unsigned)(y * WIDTH + x);

    const float4 v = __ldg(in + (size_t)p * DVEC + dv);
    float4* __restrict__ base = out + (size_t)p * ROWV + dv;

    if ((unsigned)(y - 3) < (unsigned)(HEIGHT - 6) &&
        (unsigned)(x - 3) < (unsigned)(WIDTH - 6)) {
        // Interior: all 49 destinations valid; descending shift order =>
        // ascending destination addresses.
        #pragma unroll
        for (int i = 6; i >= 0; --i) {
            #pragma unroll
            for (int j = 6; j >= 0; --j) {
                const int k = i * 7 + j;
                const int off = -(((i - 3) * WIDTH) + (j - 3)) * ROWV + k * DVEC;
                __stcs(base + off, v);
            }
        }
    } else {
        const float4 z = make_float4(0.f, 0.f, 0.f, 0.f);
        #pragma unroll
        for (int i = 6; i >= 0; --i) {
            const bool src_yok = (unsigned)(y + (i - 3)) < (unsigned)HEIGHT;
            const bool dst_yok = (unsigned)(y - (i - 3)) < (unsigned)HEIGHT;
            #pragma unroll
            for (int j = 6; j >= 0; --j) {
                const int k = i * 7 + j;
                const bool dst_ok = dst_yok && ((unsigned)(x - (j - 3)) < (unsigned)WIDTH);
                const bool src_ok = src_yok && ((unsigned)(x + (j - 3)) < (unsigned)WIDTH);

                const int off = -(((i - 3) * WIDTH) + (j - 3)) * ROWV + k * DVEC;
                if (dst_ok) __stcs(base + off, v);        // scatter my value
                if (!src_ok) __stcs(base + k * DVEC, z);  // zero-fill my OOB tap
            }
        }
    }
}

extern "C" void kernel_launch(void* const* d_in, const int* in_sizes, int n_in,
                              void* d_out, int out_size)
{
    const float4* in = (const float4*)d_in[0];
    float4* out = (float4*)d_out;
    (void)out_size;

    dim3 grid(WIDTH / 16, HEIGHT, 16);   // (3, 48, 16) -> 2304 CTAs
    local_scatter_final_kernel<<<grid, 256>>>(in, out);
}